// round 14
// baseline (speedup 1.0000x reference)
#include <cuda_runtime.h>

// Problem constants
#define NPTS   16384
#define NCHAN  64
#define DX     100
#define DY     88
#define DZ     80
#define PLANE  (DX*DY*DZ)          // 704000 floats per channel plane

// 2 threads per point -> 32768 threads = 128 blocks * 256 (single wave).
// CONVERGED CONFIG (rounds 3-13; reproduced 5x, kernel 42.2-43.2 us):
//   - traffic pinned at distinct-128B-line floor (237 MB; DRAM fill granularity
//     is 128B regardless of cache operator: .ca == plain == .cg == __ldg)
//   - BW pinned at the random-line DRAM ceiling (~5.6 TB/s), independent of
//     occupancy (12.5%..43%), SM spread (128 vs 148), and request order
//     (voxel-sorted gather tested and rejected, R8)
//   - channel-lockstep walk keeps the concurrent window ~16 planes (~59 MB),
//     below L2, capturing ALL cross-point line reuse (wider windows: +28% traffic)
#define TPB    256
#define GRID   (NPTS * 2 / TPB)    // 128

__device__ float        g_partials[GRID];
__device__ unsigned int g_count = 0;

__device__ __forceinline__ int redirect(int v, int idx0, int m) {
    int r = (v - idx0) % m;
    return (r < 0) ? r + m : r;
}

__device__ __forceinline__ int voxel_index(const int* __restrict__ pts, int b) {
    const int x = redirect(pts[b*3+0],  25, DX);
    const int y = redirect(pts[b*3+1], 225, DY);
    const int z = redirect(pts[b*3+2],  28, DZ);
    return x*(DY*DZ) + y*DZ + z;
}

__global__ void __launch_bounds__(TPB, 1)
ccl_kernel(const float* __restrict__ fixf,
           const float* __restrict__ movf,
           const int*   __restrict__ fp,
           const int*   __restrict__ pp,
           const int*   __restrict__ np_,
           float*       __restrict__ out)
{
    const int tid  = blockIdx.x * TPB + threadIdx.x;
    const int b    = tid >> 1;          // point id
    const int half = tid & 1;           // channel half: 0 -> [0,32), 1 -> [32,64)

    const int fv = voxel_index(fp,  b);
    const int pv = voxel_index(pp,  b);
    const int nv = voxel_index(np_, b);

    const float* __restrict__ pf = fixf + fv + half * 32 * PLANE;
    const float* __restrict__ pq = movf + pv + half * 32 * PLANE;
    const float* __restrict__ pn = movf + nv + half * 32 * PLANE;

    // Chip-wide lockstep channel walk; unroll 8 -> ~24 independent loads in
    // flight per thread (miss-queue saturating) with an L2-fitting footprint.
    float dpos = 0.0f, dneg = 0.0f;
#pragma unroll 8
    for (int c = 0; c < 32; c++) {
        const float f = __ldg(pf + c * PLANE);
        const float p = __ldg(pq + c * PLANE);
        const float n = __ldg(pn + c * PLANE);
        const float dp = f - p;
        const float dn = f - n;
        dpos = fmaf(dp, dp, dpos);
        dneg = fmaf(dn, dn, dneg);
    }

    // Combine the two channel-halves of this point (adjacent lanes).
    dpos += __shfl_xor_sync(0xffffffffu, dpos, 1);
    dneg += __shfl_xor_sync(0xffffffffu, dneg, 1);

    // Per-point loss, predicated to the even lane (odd lane contributes 0).
    const float lp = dpos * dpos;
    float t = fmaxf(1.0f - sqrtf(dneg), 0.0f);       // MARGIN = 1.0
    float loss = (half == 0) ? (lp + t * t) : 0.0f;

    // Warp reduce the losses (16 points per warp).
#pragma unroll
    for (int off = 16; off > 0; off >>= 1)
        loss += __shfl_xor_sync(0xffffffffu, loss, off);

    __shared__ float s_loss[TPB / 32];
    const int warp = threadIdx.x >> 5;
    const int lane = threadIdx.x & 31;
    if (lane == 0) s_loss[warp] = loss;
    __syncthreads();

    __shared__ bool s_last;
    if (threadIdx.x == 0) {
        float acc = 0.0f;
#pragma unroll
        for (int i = 0; i < TPB / 32; i++) acc += s_loss[i];
        g_partials[blockIdx.x] = acc;
        __threadfence();
        unsigned int prev = atomicAdd(&g_count, 1u);
        s_last = (prev == GRID - 1);
    }
    __syncthreads();

    if (s_last) {
        // Final deterministic reduction over GRID=128 partials.
        __shared__ float s_red[128];
        if (threadIdx.x < 128) s_red[threadIdx.x] = g_partials[threadIdx.x];
        __syncthreads();
#pragma unroll
        for (int off = 64; off > 0; off >>= 1) {
            if (threadIdx.x < off) s_red[threadIdx.x] += s_red[threadIdx.x + off];
            __syncthreads();
        }
        if (threadIdx.x == 0) {
            // loss = sum / (2 * 2B) * 1e6
            out[0] = s_red[0] * (1000000.0f / (4.0f * (float)NPTS));
            g_count = 0;   // reset for graph replay
        }
    }
}

extern "C" void kernel_launch(void* const* d_in, const int* in_sizes, int n_in,
                              void* d_out, int out_size)
{
    const float* fixf = (const float*)d_in[0];
    const float* movf = (const float*)d_in[1];
    const int*   fp   = (const int*)d_in[2];
    const int*   pp   = (const int*)d_in[3];
    const int*   np_  = (const int*)d_in[4];
    float* out = (float*)d_out;

    ccl_kernel<<<GRID, TPB>>>(fixf, movf, fp, pp, np_, out);
}

// round 15
// speedup vs baseline: 1.0059x; 1.0059x over previous
#include <cuda_runtime.h>

// Problem constants
#define NPTS   16384
#define NCHAN  64
#define DX     100
#define DY     88
#define DZ     80
#define PLANE  (DX*DY*DZ)          // 704000 floats per channel plane

// 2 threads per point -> 32768 threads = 128 blocks * 256 (single wave).
// CONVERGED CONFIG (rounds 3-14; reproduced 6x, kernel 42.2-43.2 us):
//   - traffic pinned at distinct-128B-line floor (237 MB; DRAM fill granularity
//     is 128B regardless of cache operator: .ca == plain == .cg == __ldg)
//   - BW pinned at the random-line miss-service ceiling (~5.6 TB/s), invariant
//     under occupancy (12.5%..43%), SM spread (128 vs 148), request order
//     (voxel-sorted gather, R8), and intra-plane address density
//   - channel-lockstep walk keeps the concurrent window ~16 planes (~59 MB),
//     below L2, capturing ALL cross-point line reuse (wider windows: +28% traffic)
#define TPB    256
#define GRID   (NPTS * 2 / TPB)    // 128

__device__ float        g_partials[GRID];
__device__ unsigned int g_count = 0;

__device__ __forceinline__ int redirect(int v, int idx0, int m) {
    int r = (v - idx0) % m;
    return (r < 0) ? r + m : r;
}

__device__ __forceinline__ int voxel_index(const int* __restrict__ pts, int b) {
    const int x = redirect(pts[b*3+0],  25, DX);
    const int y = redirect(pts[b*3+1], 225, DY);
    const int z = redirect(pts[b*3+2],  28, DZ);
    return x*(DY*DZ) + y*DZ + z;
}

__global__ void __launch_bounds__(TPB, 1)
ccl_kernel(const float* __restrict__ fixf,
           const float* __restrict__ movf,
           const int*   __restrict__ fp,
           const int*   __restrict__ pp,
           const int*   __restrict__ np_,
           float*       __restrict__ out)
{
    const int tid  = blockIdx.x * TPB + threadIdx.x;
    const int b    = tid >> 1;          // point id
    const int half = tid & 1;           // channel half: 0 -> [0,32), 1 -> [32,64)

    const int fv = voxel_index(fp,  b);
    const int pv = voxel_index(pp,  b);
    const int nv = voxel_index(np_, b);

    const float* __restrict__ pf = fixf + fv + half * 32 * PLANE;
    const float* __restrict__ pq = movf + pv + half * 32 * PLANE;
    const float* __restrict__ pn = movf + nv + half * 32 * PLANE;

    // Chip-wide lockstep channel walk; unroll 8 -> ~24 independent loads in
    // flight per thread (miss-queue saturating) with an L2-fitting footprint.
    float dpos = 0.0f, dneg = 0.0f;
#pragma unroll 8
    for (int c = 0; c < 32; c++) {
        const float f = __ldg(pf + c * PLANE);
        const float p = __ldg(pq + c * PLANE);
        const float n = __ldg(pn + c * PLANE);
        const float dp = f - p;
        const float dn = f - n;
        dpos = fmaf(dp, dp, dpos);
        dneg = fmaf(dn, dn, dneg);
    }

    // Combine the two channel-halves of this point (adjacent lanes).
    dpos += __shfl_xor_sync(0xffffffffu, dpos, 1);
    dneg += __shfl_xor_sync(0xffffffffu, dneg, 1);

    // Per-point loss, predicated to the even lane (odd lane contributes 0).
    const float lp = dpos * dpos;
    float t = fmaxf(1.0f - sqrtf(dneg), 0.0f);       // MARGIN = 1.0
    float loss = (half == 0) ? (lp + t * t) : 0.0f;

    // Warp reduce the losses (16 points per warp).
#pragma unroll
    for (int off = 16; off > 0; off >>= 1)
        loss += __shfl_xor_sync(0xffffffffu, loss, off);

    __shared__ float s_loss[TPB / 32];
    const int warp = threadIdx.x >> 5;
    const int lane = threadIdx.x & 31;
    if (lane == 0) s_loss[warp] = loss;
    __syncthreads();

    __shared__ bool s_last;
    if (threadIdx.x == 0) {
        float acc = 0.0f;
#pragma unroll
        for (int i = 0; i < TPB / 32; i++) acc += s_loss[i];
        g_partials[blockIdx.x] = acc;
        __threadfence();
        unsigned int prev = atomicAdd(&g_count, 1u);
        s_last = (prev == GRID - 1);
    }
    __syncthreads();

    if (s_last) {
        // Final deterministic reduction over GRID=128 partials.
        __shared__ float s_red[128];
        if (threadIdx.x < 128) s_red[threadIdx.x] = g_partials[threadIdx.x];
        __syncthreads();
#pragma unroll
        for (int off = 64; off > 0; off >>= 1) {
            if (threadIdx.x < off) s_red[threadIdx.x] += s_red[threadIdx.x + off];
            __syncthreads();
        }
        if (threadIdx.x == 0) {
            // loss = sum / (2 * 2B) * 1e6
            out[0] = s_red[0] * (1000000.0f / (4.0f * (float)NPTS));
            g_count = 0;   // reset for graph replay
        }
    }
}

extern "C" void kernel_launch(void* const* d_in, const int* in_sizes, int n_in,
                              void* d_out, int out_size)
{
    const float* fixf = (const float*)d_in[0];
    const float* movf = (const float*)d_in[1];
    const int*   fp   = (const int*)d_in[2];
    const int*   pp   = (const int*)d_in[3];
    const int*   np_  = (const int*)d_in[4];
    float* out = (float*)d_out;

    ccl_kernel<<<GRID, TPB>>>(fixf, movf, fp, pp, np_, out);
}

// round 16
// speedup vs baseline: 1.0163x; 1.0104x over previous
#include <cuda_runtime.h>

// Problem constants
#define NPTS   16384
#define NCHAN  64
#define DX     100
#define DY     88
#define DZ     80
#define PLANE  (DX*DY*DZ)          // 704000 floats per channel plane

// 2 threads per point -> 32768 threads = 128 blocks * 256 (single wave).
// CONVERGED CONFIG (rounds 3-15; reproduced 7x, kernel 42.2-43.2 us, mean 42.7):
//   - traffic pinned at distinct-128B-line floor (237 MB; DRAM fill granularity
//     is 128B regardless of cache operator: .ca == plain == .cg == __ldg)
//   - BW pinned at the random-line miss-service ceiling (~5.6 TB/s), invariant
//     under occupancy (12.5%..43%), SM spread (128 vs 148), request order
//     (voxel-sorted gather, R8), and intra-plane address density
//   - channel-lockstep walk keeps the concurrent window ~16 planes (~59 MB),
//     below L2, capturing ALL cross-point line reuse (wider windows: +28% traffic)
#define TPB    256
#define GRID   (NPTS * 2 / TPB)    // 128

__device__ float        g_partials[GRID];
__device__ unsigned int g_count = 0;

__device__ __forceinline__ int redirect(int v, int idx0, int m) {
    int r = (v - idx0) % m;
    return (r < 0) ? r + m : r;
}

__device__ __forceinline__ int voxel_index(const int* __restrict__ pts, int b) {
    const int x = redirect(pts[b*3+0],  25, DX);
    const int y = redirect(pts[b*3+1], 225, DY);
    const int z = redirect(pts[b*3+2],  28, DZ);
    return x*(DY*DZ) + y*DZ + z;
}

__global__ void __launch_bounds__(TPB, 1)
ccl_kernel(const float* __restrict__ fixf,
           const float* __restrict__ movf,
           const int*   __restrict__ fp,
           const int*   __restrict__ pp,
           const int*   __restrict__ np_,
           float*       __restrict__ out)
{
    const int tid  = blockIdx.x * TPB + threadIdx.x;
    const int b    = tid >> 1;          // point id
    const int half = tid & 1;           // channel half: 0 -> [0,32), 1 -> [32,64)

    const int fv = voxel_index(fp,  b);
    const int pv = voxel_index(pp,  b);
    const int nv = voxel_index(np_, b);

    const float* __restrict__ pf = fixf + fv + half * 32 * PLANE;
    const float* __restrict__ pq = movf + pv + half * 32 * PLANE;
    const float* __restrict__ pn = movf + nv + half * 32 * PLANE;

    // Chip-wide lockstep channel walk; unroll 8 -> ~24 independent loads in
    // flight per thread (miss-queue saturating) with an L2-fitting footprint.
    float dpos = 0.0f, dneg = 0.0f;
#pragma unroll 8
    for (int c = 0; c < 32; c++) {
        const float f = __ldg(pf + c * PLANE);
        const float p = __ldg(pq + c * PLANE);
        const float n = __ldg(pn + c * PLANE);
        const float dp = f - p;
        const float dn = f - n;
        dpos = fmaf(dp, dp, dpos);
        dneg = fmaf(dn, dn, dneg);
    }

    // Combine the two channel-halves of this point (adjacent lanes).
    dpos += __shfl_xor_sync(0xffffffffu, dpos, 1);
    dneg += __shfl_xor_sync(0xffffffffu, dneg, 1);

    // Per-point loss, predicated to the even lane (odd lane contributes 0).
    const float lp = dpos * dpos;
    float t = fmaxf(1.0f - sqrtf(dneg), 0.0f);       // MARGIN = 1.0
    float loss = (half == 0) ? (lp + t * t) : 0.0f;

    // Warp reduce the losses (16 points per warp).
#pragma unroll
    for (int off = 16; off > 0; off >>= 1)
        loss += __shfl_xor_sync(0xffffffffu, loss, off);

    __shared__ float s_loss[TPB / 32];
    const int warp = threadIdx.x >> 5;
    const int lane = threadIdx.x & 31;
    if (lane == 0) s_loss[warp] = loss;
    __syncthreads();

    __shared__ bool s_last;
    if (threadIdx.x == 0) {
        float acc = 0.0f;
#pragma unroll
        for (int i = 0; i < TPB / 32; i++) acc += s_loss[i];
        g_partials[blockIdx.x] = acc;
        __threadfence();
        unsigned int prev = atomicAdd(&g_count, 1u);
        s_last = (prev == GRID - 1);
    }
    __syncthreads();

    if (s_last) {
        // Final deterministic reduction over GRID=128 partials.
        __shared__ float s_red[128];
        if (threadIdx.x < 128) s_red[threadIdx.x] = g_partials[threadIdx.x];
        __syncthreads();
#pragma unroll
        for (int off = 64; off > 0; off >>= 1) {
            if (threadIdx.x < off) s_red[threadIdx.x] += s_red[threadIdx.x + off];
            __syncthreads();
        }
        if (threadIdx.x == 0) {
            // loss = sum / (2 * 2B) * 1e6
            out[0] = s_red[0] * (1000000.0f / (4.0f * (float)NPTS));
            g_count = 0;   // reset for graph replay
        }
    }
}

extern "C" void kernel_launch(void* const* d_in, const int* in_sizes, int n_in,
                              void* d_out, int out_size)
{
    const float* fixf = (const float*)d_in[0];
    const float* movf = (const float*)d_in[1];
    const int*   fp   = (const int*)d_in[2];
    const int*   pp   = (const int*)d_in[3];
    const int*   np_  = (const int*)d_in[4];
    float* out = (float*)d_out;

    ccl_kernel<<<GRID, TPB>>>(fixf, movf, fp, pp, np_, out);
}

// round 17
// speedup vs baseline: 1.0564x; 1.0394x over previous
#include <cuda_runtime.h>

// Problem constants
#define NPTS   16384
#define NCHAN  64
#define DX     100
#define DY     88
#define DZ     80
#define PLANE  (DX*DY*DZ)          // 704000 floats per channel plane

// 2 threads per point -> 32768 threads = 128 blocks * 256 (single wave).
// CONVERGED CONFIG (rounds 3-16; reproduced 8x, kernel 42.2-43.4 us):
//   - traffic pinned at distinct-128B-line floor (237 MB; DRAM fill granularity
//     is 128B regardless of cache operator: .ca == plain == .cg == __ldg)
//   - BW pinned at the random-line miss-service ceiling (~5.6 TB/s), invariant
//     under occupancy (12.5%..43%), SM spread (128 vs 148), request order
//     (voxel-sorted gather, R8), and intra-plane address density
//   - channel-lockstep walk keeps the concurrent window ~16 planes (~59 MB),
//     below L2, capturing ALL cross-point line reuse (wider windows: +28% traffic)
#define TPB    256
#define GRID   (NPTS * 2 / TPB)    // 128

__device__ float        g_partials[GRID];
__device__ unsigned int g_count = 0;

__device__ __forceinline__ int redirect(int v, int idx0, int m) {
    int r = (v - idx0) % m;
    return (r < 0) ? r + m : r;
}

__device__ __forceinline__ int voxel_index(const int* __restrict__ pts, int b) {
    const int x = redirect(pts[b*3+0],  25, DX);
    const int y = redirect(pts[b*3+1], 225, DY);
    const int z = redirect(pts[b*3+2],  28, DZ);
    return x*(DY*DZ) + y*DZ + z;
}

__global__ void __launch_bounds__(TPB, 1)
ccl_kernel(const float* __restrict__ fixf,
           const float* __restrict__ movf,
           const int*   __restrict__ fp,
           const int*   __restrict__ pp,
           const int*   __restrict__ np_,
           float*       __restrict__ out)
{
    const int tid  = blockIdx.x * TPB + threadIdx.x;
    const int b    = tid >> 1;          // point id
    const int half = tid & 1;           // channel half: 0 -> [0,32), 1 -> [32,64)

    const int fv = voxel_index(fp,  b);
    const int pv = voxel_index(pp,  b);
    const int nv = voxel_index(np_, b);

    const float* __restrict__ pf = fixf + fv + half * 32 * PLANE;
    const float* __restrict__ pq = movf + pv + half * 32 * PLANE;
    const float* __restrict__ pn = movf + nv + half * 32 * PLANE;

    // Chip-wide lockstep channel walk; unroll 8 -> ~24 independent loads in
    // flight per thread (miss-queue saturating) with an L2-fitting footprint.
    float dpos = 0.0f, dneg = 0.0f;
#pragma unroll 8
    for (int c = 0; c < 32; c++) {
        const float f = __ldg(pf + c * PLANE);
        const float p = __ldg(pq + c * PLANE);
        const float n = __ldg(pn + c * PLANE);
        const float dp = f - p;
        const float dn = f - n;
        dpos = fmaf(dp, dp, dpos);
        dneg = fmaf(dn, dn, dneg);
    }

    // Combine the two channel-halves of this point (adjacent lanes).
    dpos += __shfl_xor_sync(0xffffffffu, dpos, 1);
    dneg += __shfl_xor_sync(0xffffffffu, dneg, 1);

    // Per-point loss, predicated to the even lane (odd lane contributes 0).
    const float lp = dpos * dpos;
    float t = fmaxf(1.0f - sqrtf(dneg), 0.0f);       // MARGIN = 1.0
    float loss = (half == 0) ? (lp + t * t) : 0.0f;

    // Warp reduce the losses (16 points per warp).
#pragma unroll
    for (int off = 16; off > 0; off >>= 1)
        loss += __shfl_xor_sync(0xffffffffu, loss, off);

    __shared__ float s_loss[TPB / 32];
    const int warp = threadIdx.x >> 5;
    const int lane = threadIdx.x & 31;
    if (lane == 0) s_loss[warp] = loss;
    __syncthreads();

    __shared__ bool s_last;
    if (threadIdx.x == 0) {
        float acc = 0.0f;
#pragma unroll
        for (int i = 0; i < TPB / 32; i++) acc += s_loss[i];
        g_partials[blockIdx.x] = acc;
        __threadfence();
        unsigned int prev = atomicAdd(&g_count, 1u);
        s_last = (prev == GRID - 1);
    }
    __syncthreads();

    if (s_last) {
        // Final deterministic reduction over GRID=128 partials.
        __shared__ float s_red[128];
        if (threadIdx.x < 128) s_red[threadIdx.x] = g_partials[threadIdx.x];
        __syncthreads();
#pragma unroll
        for (int off = 64; off > 0; off >>= 1) {
            if (threadIdx.x < off) s_red[threadIdx.x] += s_red[threadIdx.x + off];
            __syncthreads();
        }
        if (threadIdx.x == 0) {
            // loss = sum / (2 * 2B) * 1e6
            out[0] = s_red[0] * (1000000.0f / (4.0f * (float)NPTS));
            g_count = 0;   // reset for graph replay
        }
    }
}

extern "C" void kernel_launch(void* const* d_in, const int* in_sizes, int n_in,
                              void* d_out, int out_size)
{
    const float* fixf = (const float*)d_in[0];
    const float* movf = (const float*)d_in[1];
    const int*   fp   = (const int*)d_in[2];
    const int*   pp   = (const int*)d_in[3];
    const int*   np_  = (const int*)d_in[4];
    float* out = (float*)d_out;

    ccl_kernel<<<GRID, TPB>>>(fixf, movf, fp, pp, np_, out);
}